// round 4
// baseline (speedup 1.0000x reference)
#include <cuda_runtime.h>

// ---------------- problem constants ----------------
#define cN0 1000000
#define cN1 40960
#define cN2 4096
#define cE1 1024000
#define cE2 40960
#define cIN 100
#define cHID 256
#define cOUT 47

// ---------------- scratch (static __device__, no allocs) ----------------
__device__ int   g_counts1[cN1];
__device__ int   g_off1[cN1 + 1];
__device__ int   g_cur1[cN1];
__device__ int   g_sorted1[cE1];
__device__ float g_agg1[(size_t)cN1 * cIN];     // 16.4 MB
__device__ float g_h1[(size_t)cN1 * cHID];      // 42 MB

__device__ int   g_counts2[cN2];
__device__ int   g_off2[cN2 + 1];
__device__ int   g_cur2[cN2];
__device__ int   g_sorted2[cE2];
__device__ float g_agg2[(size_t)cN2 * cHID];    // 4.2 MB

// ---------------- CSR build ----------------
__global__ void zero_counts_kernel() {
    int i = blockIdx.x * blockDim.x + threadIdx.x;
    if (i < cN1) g_counts1[i] = 0;
    if (i < cN2) g_counts2[i] = 0;
}

// NOTE: edge indices are int32 (JAX w/o x64 downcasts jnp.int64 -> int32)
__global__ void hist_kernel(const int* __restrict__ dst, int E, int ndst, int layer) {
    int i = blockIdx.x * blockDim.x + threadIdx.x;
    if (i < E) {
        int d = dst[i];
        if (d >= 0 && d < ndst) {
            if (layer == 0) atomicAdd(&g_counts1[d], 1);
            else            atomicAdd(&g_counts2[d], 1);
        }
    }
}

// single-block exclusive scan (warp-shuffle based), writes offsets + cursor copy
__global__ void scan_kernel(int layer) {
    const int* counts = layer ? g_counts2 : g_counts1;
    int* off = layer ? g_off2 : g_off1;
    int* cur = layer ? g_cur2 : g_cur1;
    int n = layer ? cN2 : cN1;

    __shared__ int wsum[32];
    __shared__ int s_carry;
    int tid = threadIdx.x;
    int lane = tid & 31, wid = tid >> 5;
    if (tid == 0) s_carry = 0;
    __syncthreads();

    for (int base = 0; base < n; base += 1024) {
        int i = base + tid;
        int v = (i < n) ? counts[i] : 0;

        int val = v;
        #pragma unroll
        for (int o = 1; o < 32; o <<= 1) {
            int t = __shfl_up_sync(0xffffffffu, val, o);
            if (lane >= o) val += t;
        }
        if (lane == 31) wsum[wid] = val;
        __syncthreads();
        if (wid == 0) {
            int s = wsum[lane];
            #pragma unroll
            for (int o = 1; o < 32; o <<= 1) {
                int t = __shfl_up_sync(0xffffffffu, s, o);
                if (lane >= o) s += t;
            }
            wsum[lane] = s;  // inclusive warp totals
        }
        __syncthreads();
        int incl = val + (wid > 0 ? wsum[wid - 1] : 0);
        int carry = s_carry;
        if (i < n) {
            int ex = carry + incl - v;
            off[i] = ex;
            cur[i] = ex;
        }
        __syncthreads();
        if (tid == 1023) s_carry = carry + incl;
        __syncthreads();
    }
    if (tid == 0) off[n] = s_carry;
}

__global__ void scatter_kernel(const int* __restrict__ src,
                               const int* __restrict__ dst, int E, int ndst, int layer) {
    int i = blockIdx.x * blockDim.x + threadIdx.x;
    if (i < E) {
        int d = dst[i];
        if (d < 0 || d >= ndst) return;
        if (layer == 0) {
            int pos = atomicAdd(&g_cur1[d], 1);
            if (pos >= 0 && pos < cE1) g_sorted1[pos] = src[i];
        } else {
            int pos = atomicAdd(&g_cur2[d], 1);
            if (pos >= 0 && pos < cE2) g_sorted2[pos] = src[i];
        }
    }
}

// ---------------- layer-1 mean aggregation ----------------
// one warp per dst node; lane<25 owns one float4 of the 100-float row
__global__ void __launch_bounds__(256) agg1_kernel(const float* __restrict__ x) {
    int gw = (blockIdx.x * blockDim.x + threadIdx.x) >> 5;
    int lane = threadIdx.x & 31;
    if (gw >= cN1) return;
    int start = g_off1[gw], end = g_off1[gw + 1];
    if (lane >= 25) return;

    const float4* x4 = (const float4*)x;
    float4 acc = make_float4(0.f, 0.f, 0.f, 0.f);
    int e = start;
    for (; e + 4 <= end; e += 4) {
        int s0 = g_sorted1[e + 0], s1 = g_sorted1[e + 1];
        int s2 = g_sorted1[e + 2], s3 = g_sorted1[e + 3];
        float4 v0 = x4[(size_t)s0 * 25 + lane];
        float4 v1 = x4[(size_t)s1 * 25 + lane];
        float4 v2 = x4[(size_t)s2 * 25 + lane];
        float4 v3 = x4[(size_t)s3 * 25 + lane];
        acc.x += v0.x; acc.y += v0.y; acc.z += v0.z; acc.w += v0.w;
        acc.x += v1.x; acc.y += v1.y; acc.z += v1.z; acc.w += v1.w;
        acc.x += v2.x; acc.y += v2.y; acc.z += v2.z; acc.w += v2.w;
        acc.x += v3.x; acc.y += v3.y; acc.z += v3.z; acc.w += v3.w;
    }
    for (; e < end; e++) {
        int s = g_sorted1[e];
        float4 v = x4[(size_t)s * 25 + lane];
        acc.x += v.x; acc.y += v.y; acc.z += v.z; acc.w += v.w;
    }
    int cnt = end - start;
    float inv = 1.f / (float)(cnt > 0 ? cnt : 1);
    acc.x *= inv; acc.y *= inv; acc.z *= inv; acc.w *= inv;
    ((float4*)g_agg1)[(size_t)gw * 25 + lane] = acc;
}

// ---------------- layer-1 fused dual GEMM: h1 = relu(agg1@W1l + x@W1r + b1l) ----------------
#define G1_BM 128
#define G1_BN 64
#define G1_BK 20
__global__ void __launch_bounds__(128) gemm1_kernel(const float* __restrict__ x,
                                                    const float* __restrict__ W1l,
                                                    const float* __restrict__ W1r,
                                                    const float* __restrict__ b1l) {
    __shared__ float As[G1_BM][G1_BK + 1];
    __shared__ float Bs[G1_BK][G1_BN];
    int tid = threadIdx.x;
    int tx = tid & 7, ty = tid >> 3;       // 8 x 16 threads, each 8x8 outputs
    int m0 = blockIdx.x * G1_BM, n0 = blockIdx.y * G1_BN;

    float acc[8][8];
    #pragma unroll
    for (int i = 0; i < 8; i++)
        #pragma unroll
        for (int j = 0; j < 8; j++) acc[i][j] = 0.f;

    for (int pass = 0; pass < 2; pass++) {
        const float* A = pass ? x : g_agg1;          // both [.., 100], rows m0..m0+127 (<40960)
        const float* B = pass ? W1r : W1l;           // [100, 256]
        for (int k0 = 0; k0 < cIN; k0 += G1_BK) {
            #pragma unroll
            for (int t = 0; t < 20; t++) {           // 128*20 = 2560 elems
                int idx = tid + t * 128;
                int r = idx / G1_BK, c = idx % G1_BK;
                As[r][c] = A[(size_t)(m0 + r) * cIN + k0 + c];
            }
            #pragma unroll
            for (int t = 0; t < 10; t++) {           // 20*64 = 1280 elems
                int idx = tid + t * 128;
                int r = idx >> 6, c = idx & 63;
                Bs[r][c] = B[(size_t)(k0 + r) * cHID + n0 + c];
            }
            __syncthreads();
            #pragma unroll
            for (int kk = 0; kk < G1_BK; kk++) {
                float a[8];
                #pragma unroll
                for (int i = 0; i < 8; i++) a[i] = As[ty * 8 + i][kk];
                float4 bv0 = *(const float4*)(&Bs[kk][tx * 8]);
                float4 bv1 = *(const float4*)(&Bs[kk][tx * 8 + 4]);
                float b[8] = {bv0.x, bv0.y, bv0.z, bv0.w, bv1.x, bv1.y, bv1.z, bv1.w};
                #pragma unroll
                for (int i = 0; i < 8; i++)
                    #pragma unroll
                    for (int j = 0; j < 8; j++) acc[i][j] += a[i] * b[j];
            }
            __syncthreads();
        }
    }

    int jbase = n0 + tx * 8;
    float bb[8];
    #pragma unroll
    for (int j = 0; j < 8; j++) bb[j] = b1l[jbase + j];
    #pragma unroll
    for (int i = 0; i < 8; i++) {
        int row = m0 + ty * 8 + i;
        float o[8];
        #pragma unroll
        for (int j = 0; j < 8; j++) o[j] = fmaxf(acc[i][j] + bb[j], 0.f);
        float* p = &g_h1[(size_t)row * cHID + jbase];
        *(float4*)p       = make_float4(o[0], o[1], o[2], o[3]);
        *(float4*)(p + 4) = make_float4(o[4], o[5], o[6], o[7]);
    }
}

// ---------------- layer-2 mean aggregation (256-wide rows, h1 mostly L2-resident) ----------------
__global__ void __launch_bounds__(256) agg2_kernel() {
    int gw = (blockIdx.x * blockDim.x + threadIdx.x) >> 5;
    int lane = threadIdx.x & 31;
    if (gw >= cN2) return;
    int start = g_off2[gw], end = g_off2[gw + 1];

    const float4* h4 = (const float4*)g_h1;
    float4 a0 = make_float4(0.f, 0.f, 0.f, 0.f);
    float4 a1 = make_float4(0.f, 0.f, 0.f, 0.f);
    int e = start;
    for (; e + 2 <= end; e += 2) {
        int s0 = g_sorted2[e], s1 = g_sorted2[e + 1];
        const float4* r0 = h4 + (size_t)s0 * 64;
        const float4* r1 = h4 + (size_t)s1 * 64;
        float4 v00 = r0[lane], v01 = r0[lane + 32];
        float4 v10 = r1[lane], v11 = r1[lane + 32];
        a0.x += v00.x; a0.y += v00.y; a0.z += v00.z; a0.w += v00.w;
        a1.x += v01.x; a1.y += v01.y; a1.z += v01.z; a1.w += v01.w;
        a0.x += v10.x; a0.y += v10.y; a0.z += v10.z; a0.w += v10.w;
        a1.x += v11.x; a1.y += v11.y; a1.z += v11.z; a1.w += v11.w;
    }
    for (; e < end; e++) {
        int s = g_sorted2[e];
        const float4* r0 = h4 + (size_t)s * 64;
        float4 v0 = r0[lane], v1 = r0[lane + 32];
        a0.x += v0.x; a0.y += v0.y; a0.z += v0.z; a0.w += v0.w;
        a1.x += v1.x; a1.y += v1.y; a1.z += v1.z; a1.w += v1.w;
    }
    int cnt = end - start;
    float inv = 1.f / (float)(cnt > 0 ? cnt : 1);
    a0.x *= inv; a0.y *= inv; a0.z *= inv; a0.w *= inv;
    a1.x *= inv; a1.y *= inv; a1.z *= inv; a1.w *= inv;
    ((float4*)g_agg2)[(size_t)gw * 64 + lane]      = a0;
    ((float4*)g_agg2)[(size_t)gw * 64 + 32 + lane] = a1;
}

// ---------------- layer-2 fused GEMM + bias + log_softmax ----------------
// 8 rows per block, out[i,j] = agg2@W2l + h1_dst@W2r + b2l, then row log_softmax
__global__ void __launch_bounds__(256) gemm2_kernel(const float* __restrict__ W2l,
                                                    const float* __restrict__ W2r,
                                                    const float* __restrict__ b2l,
                                                    float* __restrict__ out) {
    __shared__ float rA[8][512];          // [row][agg2(256) | h1(256)]
    __shared__ float svals[8][48];
    __shared__ float smax[8], slse[8];
    int tid = threadIdx.x;
    int row0 = blockIdx.x * 8;

    for (int i = tid; i < 8 * 512; i += 256) {
        int r = i >> 9, k = i & 511;
        rA[r][k] = (k < 256) ? g_agg2[(size_t)(row0 + r) * 256 + k]
                             : g_h1[(size_t)(row0 + r) * 256 + (k - 256)];
    }
    __syncthreads();

    int j = tid & 63, g = tid >> 6;
    int r0 = g * 2, r1 = g * 2 + 1;
    if (j < cOUT) {
        float acc0 = 0.f, acc1 = 0.f;
        #pragma unroll 4
        for (int k = 0; k < 256; k++) {
            float w = __ldg(&W2l[k * cOUT + j]);
            acc0 += rA[r0][k] * w;
            acc1 += rA[r1][k] * w;
        }
        #pragma unroll 4
        for (int k = 0; k < 256; k++) {
            float w = __ldg(&W2r[k * cOUT + j]);
            acc0 += rA[r0][256 + k] * w;
            acc1 += rA[r1][256 + k] * w;
        }
        float bbv = __ldg(&b2l[j]);
        svals[r0][j] = acc0 + bbv;
        svals[r1][j] = acc1 + bbv;
    }
    __syncthreads();
    if (tid < 8) {
        float m = -1e30f;
        for (int c = 0; c < cOUT; c++) m = fmaxf(m, svals[tid][c]);
        float s = 0.f;
        for (int c = 0; c < cOUT; c++) s += expf(svals[tid][c] - m);
        smax[tid] = m;
        slse[tid] = logf(s);
    }
    __syncthreads();
    for (int o = tid; o < 8 * cOUT; o += 256) {
        int r = o / cOUT, c = o % cOUT;
        out[(size_t)(row0 + r) * cOUT + c] = svals[r][c] - smax[r] - slse[r];
    }
}

// ---------------- launch ----------------
extern "C" void kernel_launch(void* const* d_in, const int* in_sizes, int n_in,
                              void* d_out, int out_size) {
    const float* x    = (const float*)d_in[0];
    const float* W1l  = (const float*)d_in[1];
    const float* b1l  = (const float*)d_in[2];
    const float* W1r  = (const float*)d_in[3];
    const float* W2l  = (const float*)d_in[4];
    const float* b2l  = (const float*)d_in[5];
    const float* W2r  = (const float*)d_in[6];
    const int*   src1 = (const int*)d_in[7];   // JAX default: int64 request -> int32 arrays
    const int*   dst1 = (const int*)d_in[8];
    const int*   src2 = (const int*)d_in[9];
    const int*   dst2 = (const int*)d_in[10];
    float* out = (float*)d_out;
    int E1 = in_sizes[7];
    int E2 = in_sizes[9];

    zero_counts_kernel<<<(cN1 + 255) / 256, 256>>>();
    hist_kernel<<<(E1 + 255) / 256, 256>>>(dst1, E1, cN1, 0);
    hist_kernel<<<(E2 + 255) / 256, 256>>>(dst2, E2, cN2, 1);
    scan_kernel<<<1, 1024>>>(0);
    scan_kernel<<<1, 1024>>>(1);
    scatter_kernel<<<(E1 + 255) / 256, 256>>>(src1, dst1, E1, cN1, 0);
    scatter_kernel<<<(E2 + 255) / 256, 256>>>(src2, dst2, E2, cN2, 1);

    agg1_kernel<<<cN1 / 8, 256>>>(x);                                   // 5120 blocks
    gemm1_kernel<<<dim3(cN1 / G1_BM, cHID / G1_BN), 128>>>(x, W1l, W1r, b1l);
    agg2_kernel<<<cN2 / 8, 256>>>();                                    // 512 blocks
    gemm2_kernel<<<cN2 / 8, 256>>>(W2l, W2r, b2l, out);                 // 512 blocks
}

// round 7
// speedup vs baseline: 1.8829x; 1.8829x over previous
#include <cuda_runtime.h>

// ---------------- problem constants ----------------
#define cN0 1000000
#define cN1 40960
#define cN2 4096
#define cE1 1024000
#define cE2 40960
#define cIN 100
#define cHID 256
#define cOUT 47

#define SCAN_B1 (cN1 / 1024)       // 40
#define SCAN_B2 (cN2 / 1024)       // 4
#define SCAN_NB (SCAN_B1 + SCAN_B2)

// ---------------- scratch (static __device__, no allocs) ----------------
__device__ int   g_counts1[cN1];
__device__ int   g_off1[cN1 + 1];
__device__ int   g_cur1[cN1];
__device__ int   g_sorted1[cE1];
__device__ float g_agg1[(size_t)cN1 * cIN];     // 16.4 MB
__device__ float g_h1[(size_t)cN1 * cHID];      // 42 MB

__device__ int   g_counts2[cN2];
__device__ int   g_off2[cN2 + 1];
__device__ int   g_cur2[cN2];
__device__ int   g_sorted2[cE2];
__device__ float g_agg2[(size_t)cN2 * cHID];    // 4.2 MB

__device__ int   g_bsum[SCAN_NB];
__device__ int   g_boff[SCAN_NB];

// ---------------- CSR build ----------------
__global__ void zero_counts_kernel() {
    int i = blockIdx.x * blockDim.x + threadIdx.x;
    if (i < cN1) g_counts1[i] = 0;
    if (i < cN2) g_counts2[i] = 0;
}

// edge indices are int32 (JAX default downcasts int64 -> int32)
__global__ void hist_all_kernel(const int* __restrict__ dst1,
                                const int* __restrict__ dst2, int E1, int E2) {
    int i = blockIdx.x * blockDim.x + threadIdx.x;
    if (i < E1) {
        int d = dst1[i];
        if (d >= 0 && d < cN1) atomicAdd(&g_counts1[d], 1);
    } else if (i < E1 + E2) {
        int d = dst2[i - E1];
        if (d >= 0 && d < cN2) atomicAdd(&g_counts2[d], 1);
    }
}

// phase 1: per-block exclusive scan, block totals to g_bsum
__global__ void __launch_bounds__(1024) scan_blocks_kernel() {
    __shared__ int wsum[32];
    int b = blockIdx.x;
    int layer = (b >= SCAN_B1);
    const int* counts = layer ? g_counts2 : g_counts1;
    int* off = layer ? g_off2 : g_off1;
    int lb = layer ? b - SCAN_B1 : b;
    int tid = threadIdx.x, lane = tid & 31, wid = tid >> 5;
    int i = lb * 1024 + tid;
    int v = counts[i];

    int val = v;
    #pragma unroll
    for (int o = 1; o < 32; o <<= 1) {
        int t = __shfl_up_sync(0xffffffffu, val, o);
        if (lane >= o) val += t;
    }
    if (lane == 31) wsum[wid] = val;
    __syncthreads();
    if (wid == 0) {
        int s = wsum[lane];
        #pragma unroll
        for (int o = 1; o < 32; o <<= 1) {
            int t = __shfl_up_sync(0xffffffffu, s, o);
            if (lane >= o) s += t;
        }
        wsum[lane] = s;
    }
    __syncthreads();
    int incl = val + (wid > 0 ? wsum[wid - 1] : 0);
    off[i] = incl - v;                  // block-local exclusive
    if (tid == 1023) g_bsum[b] = incl;  // block total
}

// phase 2: scan the 44 block totals (two independent segments)
__global__ void scan_sums_kernel() {
    __shared__ int w0;
    __shared__ int seg0;
    int tid = threadIdx.x;  // 64 threads
    int lane = tid & 31, wid = tid >> 5;
    int v = (tid < SCAN_NB) ? g_bsum[tid] : 0;
    int incl = v;
    #pragma unroll
    for (int o = 1; o < 32; o <<= 1) {
        int t = __shfl_up_sync(0xffffffffu, incl, o);
        if (lane >= o) incl += t;
    }
    if (wid == 0 && lane == 31) w0 = incl;
    __syncthreads();
    int inclg = incl + (wid ? w0 : 0);
    if (tid == SCAN_B1 - 1) seg0 = inclg;
    __syncthreads();
    if (tid < SCAN_B1) {
        g_boff[tid] = inclg - v;
        if (tid == SCAN_B1 - 1) g_off1[cN1] = inclg;
    } else if (tid < SCAN_NB) {
        g_boff[tid] = inclg - v - seg0;
        if (tid == SCAN_NB - 1) g_off2[cN2] = inclg - seg0;
    }
}

// phase 3: add block offsets, fill cursors
__global__ void __launch_bounds__(1024) scan_add_kernel() {
    int b = blockIdx.x;
    int layer = (b >= SCAN_B1);
    int* off = layer ? g_off2 : g_off1;
    int* cur = layer ? g_cur2 : g_cur1;
    int lb = layer ? b - SCAN_B1 : b;
    int i = lb * 1024 + threadIdx.x;
    int v = off[i] + g_boff[b];
    off[i] = v;
    cur[i] = v;
}

__global__ void scatter_all_kernel(const int* __restrict__ src1,
                                   const int* __restrict__ dst1,
                                   const int* __restrict__ src2,
                                   const int* __restrict__ dst2, int E1, int E2) {
    int i = blockIdx.x * blockDim.x + threadIdx.x;
    if (i < E1) {
        int d = dst1[i];
        if (d < 0 || d >= cN1) return;
        int pos = atomicAdd(&g_cur1[d], 1);
        if (pos >= 0 && pos < cE1) g_sorted1[pos] = src1[i];
    } else if (i < E1 + E2) {
        int d = dst2[i - E1];
        if (d < 0 || d >= cN2) return;
        int pos = atomicAdd(&g_cur2[d], 1);
        if (pos >= 0 && pos < cE2) g_sorted2[pos] = src2[i - E1];
    }
}

// ---------------- layer-1 mean aggregation ----------------
// one warp per dst node; lane<25 owns one float4 of the 100-float row
__global__ void __launch_bounds__(256) agg1_kernel(const float* __restrict__ x) {
    int gw = (blockIdx.x * blockDim.x + threadIdx.x) >> 5;
    int lane = threadIdx.x & 31;
    if (gw >= cN1) return;
    int start = g_off1[gw], end = g_off1[gw + 1];
    if (lane >= 25) return;

    const float4* x4 = (const float4*)x;
    float4 acc = make_float4(0.f, 0.f, 0.f, 0.f);
    int e = start;
    for (; e + 4 <= end; e += 4) {
        int s0 = g_sorted1[e + 0], s1 = g_sorted1[e + 1];
        int s2 = g_sorted1[e + 2], s3 = g_sorted1[e + 3];
        float4 v0 = x4[(size_t)s0 * 25 + lane];
        float4 v1 = x4[(size_t)s1 * 25 + lane];
        float4 v2 = x4[(size_t)s2 * 25 + lane];
        float4 v3 = x4[(size_t)s3 * 25 + lane];
        acc.x += v0.x; acc.y += v0.y; acc.z += v0.z; acc.w += v0.w;
        acc.x += v1.x; acc.y += v1.y; acc.z += v1.z; acc.w += v1.w;
        acc.x += v2.x; acc.y += v2.y; acc.z += v2.z; acc.w += v2.w;
        acc.x += v3.x; acc.y += v3.y; acc.z += v3.z; acc.w += v3.w;
    }
    for (; e < end; e++) {
        int s = g_sorted1[e];
        float4 v = x4[(size_t)s * 25 + lane];
        acc.x += v.x; acc.y += v.y; acc.z += v.z; acc.w += v.w;
    }
    int cnt = end - start;
    float inv = 1.f / (float)(cnt > 0 ? cnt : 1);
    acc.x *= inv; acc.y *= inv; acc.z *= inv; acc.w *= inv;
    ((float4*)g_agg1)[(size_t)gw * 25 + lane] = acc;
}

// ---------------- layer-1 fused dual GEMM via tf32 tensor cores ----------------
// h1 = relu(agg1@W1l + x@W1r + b1l)  [40960x256], K=100 per pass
__device__ __forceinline__ unsigned f2tf32(float f) {
    unsigned u;
    asm("cvt.rna.tf32.f32 %0, %1;" : "=r"(u) : "f"(f));
    return u;
}

#define GM_BM 128
#define GM_BN 128
#define GM_BK 32
#define AS_LD 36
#define BS_LD 136

__global__ void __launch_bounds__(256) gemm1_mma_kernel(const float* __restrict__ x,
                                                        const float* __restrict__ W1l,
                                                        const float* __restrict__ W1r,
                                                        const float* __restrict__ b1l) {
    __shared__ unsigned As[GM_BM][AS_LD];   // tf32 bits, padded
    __shared__ unsigned Bs[GM_BK][BS_LD];
    int tid = threadIdx.x;
    int lane = tid & 31, warp = tid >> 5;
    int warpM = warp & 3, warpN = warp >> 2;      // 4 x 2 warps, 32x64 warp tile
    int g = lane >> 2, t = lane & 3;
    int m0 = blockIdx.x * GM_BM, n0 = blockIdx.y * GM_BN;

    float acc[2][8][4];
    #pragma unroll
    for (int mt = 0; mt < 2; mt++)
        #pragma unroll
        for (int nt = 0; nt < 8; nt++)
            #pragma unroll
            for (int q = 0; q < 4; q++) acc[mt][nt][q] = 0.f;

    for (int pass = 0; pass < 2; pass++) {
        const float* A = pass ? x : g_agg1;       // [rows, 100], rows m0..m0+127 < 40960
        const float* B = pass ? W1r : W1l;        // [100, 256]
        for (int k0 = 0; k0 < 128; k0 += GM_BK) { // K padded 100 -> 128 with zeros
            // load A tile [128 x 32]
            #pragma unroll
            for (int it = 0; it < 16; it++) {
                int idx = tid + it * 256;
                int r = idx >> 5, c = idx & 31;
                float v = (k0 + c < cIN) ? A[(size_t)(m0 + r) * cIN + k0 + c] : 0.f;
                As[r][c] = f2tf32(v);
            }
            // load B tile [32 x 128]
            #pragma unroll
            for (int it = 0; it < 16; it++) {
                int idx = tid + it * 256;
                int r = idx >> 7, c = idx & 127;
                float v = (k0 + r < cIN) ? B[(size_t)(k0 + r) * cHID + n0 + c] : 0.f;
                Bs[r][c] = f2tf32(v);
            }
            __syncthreads();
            #pragma unroll
            for (int ks = 0; ks < 4; ks++) {
                int k = ks * 8;
                unsigned af[2][4], bf[8][2];
                #pragma unroll
                for (int mt = 0; mt < 2; mt++) {
                    int rb = warpM * 32 + mt * 16 + g;
                    af[mt][0] = As[rb][k + t];
                    af[mt][1] = As[rb + 8][k + t];
                    af[mt][2] = As[rb][k + t + 4];
                    af[mt][3] = As[rb + 8][k + t + 4];
                }
                #pragma unroll
                for (int nt = 0; nt < 8; nt++) {
                    int cb = warpN * 64 + nt * 8 + g;
                    bf[nt][0] = Bs[k + t][cb];
                    bf[nt][1] = Bs[k + t + 4][cb];
                }
                #pragma unroll
                for (int mt = 0; mt < 2; mt++)
                    #pragma unroll
                    for (int nt = 0; nt < 8; nt++) {
                        asm volatile(
                            "mma.sync.aligned.m16n8k8.row.col.f32.tf32.tf32.f32 "
                            "{%0,%1,%2,%3}, {%4,%5,%6,%7}, {%8,%9}, {%0,%1,%2,%3};"
                            : "+f"(acc[mt][nt][0]), "+f"(acc[mt][nt][1]),
                              "+f"(acc[mt][nt][2]), "+f"(acc[mt][nt][3])
                            : "r"(af[mt][0]), "r"(af[mt][1]), "r"(af[mt][2]), "r"(af[mt][3]),
                              "r"(bf[nt][0]), "r"(bf[nt][1]));
                    }
            }
            __syncthreads();
        }
    }

    // epilogue: bias + relu, store to g_h1
    #pragma unroll
    for (int nt = 0; nt < 8; nt++) {
        int col = n0 + warpN * 64 + nt * 8 + t * 2;
        float b0v = b1l[col], b1v = b1l[col + 1];
        #pragma unroll
        for (int mt = 0; mt < 2; mt++) {
            int row = m0 + warpM * 32 + mt * 16 + g;
            float2 o0, o1;
            o0.x = fmaxf(acc[mt][nt][0] + b0v, 0.f);
            o0.y = fmaxf(acc[mt][nt][1] + b1v, 0.f);
            o1.x = fmaxf(acc[mt][nt][2] + b0v, 0.f);
            o1.y = fmaxf(acc[mt][nt][3] + b1v, 0.f);
            *(float2*)&g_h1[(size_t)row * cHID + col] = o0;
            *(float2*)&g_h1[(size_t)(row + 8) * cHID + col] = o1;
        }
    }
}

// ---------------- layer-2 mean aggregation ----------------
__global__ void __launch_bounds__(256) agg2_kernel() {
    int gw = (blockIdx.x * blockDim.x + threadIdx.x) >> 5;
    int lane = threadIdx.x & 31;
    if (gw >= cN2) return;
    int start = g_off2[gw], end = g_off2[gw + 1];

    const float4* h4 = (const float4*)g_h1;
    float4 a0 = make_float4(0.f, 0.f, 0.f, 0.f);
    float4 a1 = make_float4(0.f, 0.f, 0.f, 0.f);
    int e = start;
    for (; e + 2 <= end; e += 2) {
        int s0 = g_sorted2[e], s1 = g_sorted2[e + 1];
        const float4* r0 = h4 + (size_t)s0 * 64;
        const float4* r1 = h4 + (size_t)s1 * 64;
        float4 v00 = r0[lane], v01 = r0[lane + 32];
        float4 v10 = r1[lane], v11 = r1[lane + 32];
        a0.x += v00.x; a0.y += v00.y; a0.z += v00.z; a0.w += v00.w;
        a1.x += v01.x; a1.y += v01.y; a1.z += v01.z; a1.w += v01.w;
        a0.x += v10.x; a0.y += v10.y; a0.z += v10.z; a0.w += v10.w;
        a1.x += v11.x; a1.y += v11.y; a1.z += v11.z; a1.w += v11.w;
    }
    for (; e < end; e++) {
        int s = g_sorted2[e];
        const float4* r0 = h4 + (size_t)s * 64;
        float4 v0 = r0[lane], v1 = r0[lane + 32];
        a0.x += v0.x; a0.y += v0.y; a0.z += v0.z; a0.w += v0.w;
        a1.x += v1.x; a1.y += v1.y; a1.z += v1.z; a1.w += v1.w;
    }
    int cnt = end - start;
    float inv = 1.f / (float)(cnt > 0 ? cnt : 1);
    a0.x *= inv; a0.y *= inv; a0.z *= inv; a0.w *= inv;
    a1.x *= inv; a1.y *= inv; a1.z *= inv; a1.w *= inv;
    ((float4*)g_agg2)[(size_t)gw * 64 + lane]      = a0;
    ((float4*)g_agg2)[(size_t)gw * 64 + 32 + lane] = a1;
}

// ---------------- layer-2 fused GEMM + bias + log_softmax ----------------
__global__ void __launch_bounds__(256) gemm2_kernel(const float* __restrict__ W2l,
                                                    const float* __restrict__ W2r,
                                                    const float* __restrict__ b2l,
                                                    float* __restrict__ out) {
    __shared__ float rA[8][512];
    __shared__ float svals[8][48];
    __shared__ float smax[8], slse[8];
    int tid = threadIdx.x;
    int row0 = blockIdx.x * 8;

    for (int i = tid; i < 8 * 512; i += 256) {
        int r = i >> 9, k = i & 511;
        rA[r][k] = (k < 256) ? g_agg2[(size_t)(row0 + r) * 256 + k]
                             : g_h1[(size_t)(row0 + r) * 256 + (k - 256)];
    }
    __syncthreads();

    int j = tid & 63, gg = tid >> 6;
    int r0 = gg * 2, r1 = gg * 2 + 1;
    if (j < cOUT) {
        float acc0 = 0.f, acc1 = 0.f;
        #pragma unroll 4
        for (int k = 0; k < 256; k++) {
            float w = __ldg(&W2l[k * cOUT + j]);
            acc0 += rA[r0][k] * w;
            acc1 += rA[r1][k] * w;
        }
        #pragma unroll 4
        for (int k = 0; k < 256; k++) {
            float w = __ldg(&W2r[k * cOUT + j]);
            acc0 += rA[r0][256 + k] * w;
            acc1 += rA[r1][256 + k] * w;
        }
        float bbv = __ldg(&b2l[j]);
        svals[r0][j] = acc0 + bbv;
        svals[r1][j] = acc1 + bbv;
    }
    __syncthreads();
    if (tid < 8) {
        float m = -1e30f;
        for (int c = 0; c < cOUT; c++) m = fmaxf(m, svals[tid][c]);
        float s = 0.f;
        for (int c = 0; c < cOUT; c++) s += expf(svals[tid][c] - m);
        smax[tid] = m;
        slse[tid] = logf(s);
    }
    __syncthreads();
    for (int o = tid; o < 8 * cOUT; o += 256) {
        int r = o / cOUT, c = o % cOUT;
        out[(size_t)(row0 + r) * cOUT + c] = svals[r][c] - smax[r] - slse[r];
    }
}

// ---------------- launch ----------------
extern "C" void kernel_launch(void* const* d_in, const int* in_sizes, int n_in,
                              void* d_out, int out_size) {
    const float* x    = (const float*)d_in[0];
    const float* W1l  = (const float*)d_in[1];
    const float* b1l  = (const float*)d_in[2];
    const float* W1r  = (const float*)d_in[3];
    const float* W2l  = (const float*)d_in[4];
    const float* b2l  = (const float*)d_in[5];
    const float* W2r  = (const float*)d_in[6];
    const int*   src1 = (const int*)d_in[7];
    const int*   dst1 = (const int*)d_in[8];
    const int*   src2 = (const int*)d_in[9];
    const int*   dst2 = (const int*)d_in[10];
    float* out = (float*)d_out;
    int E1 = in_sizes[7];
    int E2 = in_sizes[9];

    zero_counts_kernel<<<(cN1 + 255) / 256, 256>>>();
    hist_all_kernel<<<(E1 + E2 + 255) / 256, 256>>>(dst1, dst2, E1, E2);
    scan_blocks_kernel<<<SCAN_NB, 1024>>>();
    scan_sums_kernel<<<1, 64>>>();
    scan_add_kernel<<<SCAN_NB, 1024>>>();
    scatter_all_kernel<<<(E1 + E2 + 255) / 256, 256>>>(src1, dst1, src2, dst2, E1, E2);

    agg1_kernel<<<cN1 / 8, 256>>>(x);
    gemm1_mma_kernel<<<dim3(cN1 / GM_BM, cHID / GM_BN), 256>>>(x, W1l, W1r, b1l);
    agg2_kernel<<<cN2 / 8, 256>>>();
    gemm2_kernel<<<cN2 / 8, 256>>>(W2l, W2r, b2l, out);
}